// round 2
// baseline (speedup 1.0000x reference)
#include <cuda_runtime.h>
#include <cstdint>

// RandomTimeMask: out[n,c,l] = x[n,c,l] if ((l - starts[n,c]) mod L) >= L/4 else 0
// Shapes: x [128, 12, 32768] fp32, starts [128, 12] int32 (JAX x64-disabled downgrade).
// L = 32768, mask_len = 8192. Pure streaming: 192 MiB in + 192 MiB out.
// One block per (n,c) row; float4 vectorized.

static constexpr int L        = 32768;
static constexpr int MASK_LEN = L / 4;       // 8192
static constexpr int LM1      = L - 1;       // 32767
static constexpr int VEC_PER_ROW = L / 4;    // 8192 float4 per row
static constexpr int THREADS  = 256;

__global__ __launch_bounds__(THREADS)
void random_time_mask_kernel(const float4* __restrict__ x,
                             const int* __restrict__ starts,
                             float4* __restrict__ out)
{
    const int row = blockIdx.x;                       // n*C + c, 0..1535
    const int s   = starts[row];                      // 0 <= s < L

    const float4* __restrict__ xr = x   + (size_t)row * VEC_PER_ROW;
    float4*       __restrict__ yr = out + (size_t)row * VEC_PER_ROW;

    // Each thread handles 32 float4s, stride = blockDim.
    #pragma unroll 4
    for (int i = threadIdx.x; i < VEC_PER_ROW; i += THREADS) {
        float4 v = xr[i];
        const int base = i << 2;                      // element index of v.x
        // circular offset from start; L power-of-two so mod == AND (two's complement safe)
        const int o0 = (base + 0 - s) & LM1;
        const int o1 = (base + 1 - s) & LM1;
        const int o2 = (base + 2 - s) & LM1;
        const int o3 = (base + 3 - s) & LM1;
        v.x = (o0 < MASK_LEN) ? 0.0f : v.x;
        v.y = (o1 < MASK_LEN) ? 0.0f : v.y;
        v.z = (o2 < MASK_LEN) ? 0.0f : v.z;
        v.w = (o3 < MASK_LEN) ? 0.0f : v.w;
        yr[i] = v;
    }
}

extern "C" void kernel_launch(void* const* d_in, const int* in_sizes, int n_in,
                              void* d_out, int out_size)
{
    const float4* x      = (const float4*)d_in[0];
    const int*    starts = (const int*)d_in[1];
    float4*       out    = (float4*)d_out;

    const int n_rows = in_sizes[1];                   // 128*12 = 1536
    random_time_mask_kernel<<<n_rows, THREADS>>>(x, starts, out);
}

// round 3
// speedup vs baseline: 1.0325x; 1.0325x over previous
#include <cuda_runtime.h>
#include <cstdint>

// RandomTimeMask: out[n,c,l] = x[n,c,l] if ((l - starts[n,c]) mod L) >= L/4 else 0
// Shapes: x [128, 12, 32768] fp32, starts [128, 12] int32. L=32768, mask_len=8192.
// HBM-bound streaming. Optimization: the masked region is one contiguous circular
// run of 8192 elements per row -> skip the GMEM *read* for fully-masked vectors
// (store literal zeros). Saves 25% of read traffic: 403 MB -> 352 MB total.

static constexpr int L        = 32768;
static constexpr int MASK_LEN = L / 4;       // 8192
static constexpr int LM1      = L - 1;       // 32767
static constexpr int VEC_PER_ROW = L / 4;    // 8192 float4 per row
static constexpr int THREADS  = 256;

__global__ __launch_bounds__(THREADS)
void random_time_mask_kernel(const float4* __restrict__ x,
                             const int* __restrict__ starts,
                             float4* __restrict__ out)
{
    const int row = blockIdx.x;                       // n*C + c, 0..1535
    const int s   = starts[row];                      // 0 <= s < L

    const float4* __restrict__ xr = x   + (size_t)row * VEC_PER_ROW;
    float4*       __restrict__ yr = out + (size_t)row * VEC_PER_ROW;

    #pragma unroll 4
    for (int i = threadIdx.x; i < VEC_PER_ROW; i += THREADS) {
        const int base = i << 2;                      // element index of v.x
        // circular offset of first lane from start (L power-of-two -> mod == AND)
        const int o0 = (base - s) & LM1;

        float4 v;
        if (o0 >= MASK_LEN && o0 <= L - 4) {
            // fully kept: straight copy
            v = xr[i];
        } else if (o0 <= MASK_LEN - 4) {
            // fully masked: no load at all
            v = make_float4(0.0f, 0.0f, 0.0f, 0.0f);
        } else {
            // boundary vector (<= 2 per row): load + per-lane select
            v = xr[i];
            const int o1 = (base + 1 - s) & LM1;
            const int o2 = (base + 2 - s) & LM1;
            const int o3 = (base + 3 - s) & LM1;
            if (o0 < MASK_LEN) v.x = 0.0f;
            if (o1 < MASK_LEN) v.y = 0.0f;
            if (o2 < MASK_LEN) v.z = 0.0f;
            if (o3 < MASK_LEN) v.w = 0.0f;
        }
        yr[i] = v;
    }
}

extern "C" void kernel_launch(void* const* d_in, const int* in_sizes, int n_in,
                              void* d_out, int out_size)
{
    const float4* x      = (const float4*)d_in[0];
    const int*    starts = (const int*)d_in[1];
    float4*       out    = (float4*)d_out;

    const int n_rows = in_sizes[1];                   // 128*12 = 1536
    random_time_mask_kernel<<<n_rows, THREADS>>>(x, starts, out);
}

// round 4
// speedup vs baseline: 1.0440x; 1.0111x over previous
#include <cuda_runtime.h>
#include <cstdint>

// RandomTimeMask: out[n,c,l] = x[n,c,l] if ((l - starts[n,c]) mod L) >= L/4 else 0
// x [128,12,32768] fp32, starts [128,12] int32. L=32768, mask_len=8192.
//
// The masked region is ONE contiguous circular run per row, so each row splits
// into <= 3 contiguous spans: zero spans (store-only, no GMEM read) and copy
// spans (branch-free streaming copy, full MLP). Saves 25% of read traffic
// (403 -> 352 MB) without the per-vector branches that killed MLP in R3.

static constexpr int L       = 32768;
static constexpr int ML      = L / 4;     // 8192
static constexpr int THREADS = 256;

__device__ __forceinline__ void zero_span(float* __restrict__ y, int a, int b)
{
    if (a >= b) return;
    const int tid = threadIdx.x;
    const int a4 = (a + 3) & ~3;
    if (a4 >= b) {                         // tiny span, scalar only
        for (int p = a + tid; p < b; p += THREADS) y[p] = 0.0f;
        return;
    }
    const int b4 = b & ~3;
    if (tid < a4 - a) y[a + tid] = 0.0f;   // head (<4 elems)
    float4* __restrict__ y4 = (float4*)y;
    const float4 z = make_float4(0.f, 0.f, 0.f, 0.f);
    #pragma unroll 4
    for (int i = (a4 >> 2) + tid; i < (b4 >> 2); i += THREADS) y4[i] = z;
    if (tid < b - b4) y[b4 + tid] = 0.0f;  // tail (<4 elems)
}

__device__ __forceinline__ void copy_span(float* __restrict__ y,
                                          const float* __restrict__ x,
                                          int a, int b)
{
    if (a >= b) return;
    const int tid = threadIdx.x;
    const int a4 = (a + 3) & ~3;
    if (a4 >= b) {
        for (int p = a + tid; p < b; p += THREADS) y[p] = x[p];
        return;
    }
    const int b4 = b & ~3;
    if (tid < a4 - a) y[a + tid] = x[a + tid];
    const float4* __restrict__ x4 = (const float4*)x;
    float4* __restrict__ y4 = (float4*)y;
    #pragma unroll 4
    for (int i = (a4 >> 2) + tid; i < (b4 >> 2); i += THREADS) y4[i] = x4[i];
    if (tid < b - b4) y[b4 + tid] = x[b4 + tid];
}

__global__ __launch_bounds__(THREADS)
void random_time_mask_kernel(const float* __restrict__ x,
                             const int* __restrict__ starts,
                             float* __restrict__ out)
{
    const int row = blockIdx.x;                       // 0..1535
    const int s   = starts[row];                      // 0 <= s < L
    const float* __restrict__ xr = x   + (size_t)row * L;
    float*       __restrict__ yr = out + (size_t)row * L;

    const int e = s + ML;                             // mask end (unwrapped)
    if (e <= L) {
        // [0,s) keep | [s,e) zero | [e,L) keep
        copy_span(yr, xr, 0, s);
        zero_span(yr, s, e);
        copy_span(yr, xr, e, L);
    } else {
        // [0,e-L) zero | [e-L,s) keep | [s,L) zero
        zero_span(yr, 0, e - L);
        copy_span(yr, xr, e - L, s);
        zero_span(yr, s, L);
    }
}

extern "C" void kernel_launch(void* const* d_in, const int* in_sizes, int n_in,
                              void* d_out, int out_size)
{
    const float* x      = (const float*)d_in[0];
    const int*   starts = (const int*)d_in[1];
    float*       out    = (float*)d_out;

    const int n_rows = in_sizes[1];                   // 128*12 = 1536
    random_time_mask_kernel<<<n_rows, THREADS>>>(x, starts, out);
}

// round 5
// speedup vs baseline: 1.0784x; 1.0329x over previous
#include <cuda_runtime.h>
#include <cstdint>

// RandomTimeMask: out[n,c,l] = x[n,c,l] if ((l - starts[n,c]) mod L) >= L/4 else 0
// x [128,12,32768] fp32, starts [128,12] int32. L=32768, mask_len=8192.
//
// Row splits into <=3 contiguous spans (zero: store-only; copy: stream).
// R5 fix: explicit 4-wide load batching inside span loops to restore MLP
// (R4's runtime-bounded loops compiled to 1 load/iter -> exposed latency,
// DRAM stuck at 68%). Streaming cache hints: no reuse, working set > L2.

static constexpr int L       = 32768;
static constexpr int ML      = L / 4;     // 8192
static constexpr int THREADS = 256;

__device__ __forceinline__ void zero_span(float* __restrict__ y, int a, int b)
{
    if (a >= b) return;
    const int tid = threadIdx.x;
    const int a4 = (a + 3) & ~3;
    if (a4 >= b) {
        for (int p = a + tid; p < b; p += THREADS) y[p] = 0.0f;
        return;
    }
    const int b4 = b & ~3;
    if (tid < a4 - a) y[a + tid] = 0.0f;
    float4* __restrict__ y4 = (float4*)y;
    const float4 z = make_float4(0.f, 0.f, 0.f, 0.f);
    int i = (a4 >> 2) + tid;
    const int n = b4 >> 2;
    for (; i + 3 * THREADS < n; i += 4 * THREADS) {
        __stcs(&y4[i],              z);
        __stcs(&y4[i +     THREADS], z);
        __stcs(&y4[i + 2 * THREADS], z);
        __stcs(&y4[i + 3 * THREADS], z);
    }
    for (; i < n; i += THREADS) __stcs(&y4[i], z);
    if (tid < b - b4) y[b4 + tid] = 0.0f;
}

__device__ __forceinline__ void copy_span(float* __restrict__ y,
                                          const float* __restrict__ x,
                                          int a, int b)
{
    if (a >= b) return;
    const int tid = threadIdx.x;
    const int a4 = (a + 3) & ~3;
    if (a4 >= b) {
        for (int p = a + tid; p < b; p += THREADS) y[p] = x[p];
        return;
    }
    const int b4 = b & ~3;
    if (tid < a4 - a) y[a + tid] = x[a + tid];
    const float4* __restrict__ x4 = (const float4*)x;
    float4* __restrict__ y4 = (float4*)y;
    int i = (a4 >> 2) + tid;
    const int n = b4 >> 2;
    // main: 4 independent loads in flight before any store
    for (; i + 3 * THREADS < n; i += 4 * THREADS) {
        float4 v0 = __ldcs(&x4[i]);
        float4 v1 = __ldcs(&x4[i +     THREADS]);
        float4 v2 = __ldcs(&x4[i + 2 * THREADS]);
        float4 v3 = __ldcs(&x4[i + 3 * THREADS]);
        __stcs(&y4[i],              v0);
        __stcs(&y4[i +     THREADS], v1);
        __stcs(&y4[i + 2 * THREADS], v2);
        __stcs(&y4[i + 3 * THREADS], v3);
    }
    for (; i < n; i += THREADS) __stcs(&y4[i], __ldcs(&x4[i]));
    if (tid < b - b4) y[b4 + tid] = x[b4 + tid];
}

__global__ __launch_bounds__(THREADS)
void random_time_mask_kernel(const float* __restrict__ x,
                             const int* __restrict__ starts,
                             float* __restrict__ out)
{
    const int row = blockIdx.x;                       // 0..1535
    const int s   = starts[row];                      // 0 <= s < L
    const float* __restrict__ xr = x   + (size_t)row * L;
    float*       __restrict__ yr = out + (size_t)row * L;

    const int e = s + ML;                             // mask end (unwrapped)
    if (e <= L) {
        copy_span(yr, xr, 0, s);
        zero_span(yr, s, e);
        copy_span(yr, xr, e, L);
    } else {
        zero_span(yr, 0, e - L);
        copy_span(yr, xr, e - L, s);
        zero_span(yr, s, L);
    }
}

extern "C" void kernel_launch(void* const* d_in, const int* in_sizes, int n_in,
                              void* d_out, int out_size)
{
    const float* x      = (const float*)d_in[0];
    const int*   starts = (const int*)d_in[1];
    float*       out    = (float*)d_out;

    const int n_rows = in_sizes[1];                   // 128*12 = 1536
    random_time_mask_kernel<<<n_rows, THREADS>>>(x, starts, out);
}

// round 6
// speedup vs baseline: 1.1026x; 1.0224x over previous
#include <cuda_runtime.h>
#include <cstdint>

// RandomTimeMask: out[n,c,l] = x[n,c,l] if ((l - starts[n,c]) mod L) >= L/4 else 0
// x [128,12,32768] fp32, starts [128,12] int32. L=32768, mask_len=8192.
//
// R6: uniform R2-style static-unroll loop (best measured DRAM rate) + predicated
// vector loads via inline PTX (@p ld.global.cs.v4) so fully-masked float4s skip
// the GMEM read without BSSY/BSYNC branches. Predicate is warp-uniform except at
// the 2 run boundaries per row -> masked warps issue no L1tex wavefronts.
// 4 blocks per row (6144 CTAs) to shrink the wave tail (1.3 -> 5.2 waves).

static constexpr int L        = 32768;
static constexpr int ML       = L / 4;        // 8192
static constexpr int LM1      = L - 1;        // 32767
static constexpr int QUARTER  = L / 4;        // 8192 elements per block
static constexpr int VEC_PER_BLK = QUARTER / 4;  // 2048 float4
static constexpr int THREADS  = 256;

__global__ __launch_bounds__(THREADS)
void random_time_mask_kernel(const float* __restrict__ x,
                             const int* __restrict__ starts,
                             float* __restrict__ out)
{
    const int row  = blockIdx.x >> 2;            // 0..1535
    const int quad = blockIdx.x & 3;             // 0..3
    const int s    = starts[row];                // 0 <= s < L

    const size_t base_elem = (size_t)row * L + (size_t)quad * QUARTER;
    const float4* __restrict__ xr = (const float4*)(x   + base_elem);
    float4*       __restrict__ yr = (float4*)      (out + base_elem);
    const int elem0 = quad * QUARTER;            // element index of this block's start

    #pragma unroll 4
    for (int i = threadIdx.x; i < VEC_PER_BLK; i += THREADS) {
        const int base = elem0 + (i << 2);       // element index of lane .x
        const int o0 = (base     - s) & LM1;     // circular offsets (L pow2)
        const int o1 = (base + 1 - s) & LM1;
        const int o2 = (base + 2 - s) & LM1;
        const int o3 = (base + 3 - s) & LM1;

        // Fully masked iff o0 <= ML-4  ->  skip the load (predicated).
        float4 v;
        v.x = 0.f; v.y = 0.f; v.z = 0.f; v.w = 0.f;
        asm("{\n\t"
            ".reg .pred p;\n\t"
            "setp.gt.s32 p, %4, %5;\n\t"
            "@p ld.global.cs.v4.f32 {%0,%1,%2,%3}, [%6];\n\t"
            "}"
            : "+f"(v.x), "+f"(v.y), "+f"(v.z), "+f"(v.w)
            : "r"(o0), "n"(ML - 4), "l"(xr + i));

        // Per-lane boundary selects (no-ops for fully kept/masked vectors).
        v.x = (o0 < ML) ? 0.0f : v.x;
        v.y = (o1 < ML) ? 0.0f : v.y;
        v.z = (o2 < ML) ? 0.0f : v.z;
        v.w = (o3 < ML) ? 0.0f : v.w;
        yr[i] = v;
    }
}

extern "C" void kernel_launch(void* const* d_in, const int* in_sizes, int n_in,
                              void* d_out, int out_size)
{
    const float* x      = (const float*)d_in[0];
    const int*   starts = (const int*)d_in[1];
    float*       out    = (float*)d_out;

    const int n_rows = in_sizes[1];               // 128*12 = 1536
    random_time_mask_kernel<<<n_rows * 4, THREADS>>>(x, starts, out);
}

// round 7
// speedup vs baseline: 1.1422x; 1.0360x over previous
#include <cuda_runtime.h>
#include <cstdint>

// RandomTimeMask: out[n,c,l] = x[n,c,l] if ((l - starts[n,c]) mod L) >= L/4 else 0
// x [128,12,32768] fp32, starts [128,12] int32. L=32768, mask_len=8192.
//
// R7: load/store pacing. The masked run is exactly 1/4 of each row, so one
// uniform loop pairs 1 zero-store vector with 3 copy vectors per iteration
// (3 LDG.128 + 4 STG.128, identical for every thread, branch-free). This
// avoids store-only bursts that clog the LSU queue and degraded read latency
// hiding in R4-R6. App traffic stays at the 336 MB minimum (144R + 192W).

static constexpr int L    = 32768;
static constexpr int ML   = 8192;         // mask_len
static constexpr int LM1  = L - 1;
static constexpr int VPR  = L / 4;        // 8192 float4 per row
static constexpr int VM1  = VPR - 1;      // 8191
static constexpr int THREADS = 256;
static constexpr int SPLITS  = 4;         // blocks per row
static constexpr int JTOT    = 2047;      // paired iterations per row
static constexpr int JSPAN   = 512;       // ceil(2047/4)

__global__ __launch_bounds__(THREADS)
void random_time_mask_kernel(const float4* __restrict__ x,
                             const int* __restrict__ starts,
                             float4* __restrict__ out)
{
    const int row   = blockIdx.x >> 2;           // 0..1535
    const int split = blockIdx.x & 3;            // 0..3
    const int s     = starts[row];               // 0 <= s < L

    const float4* __restrict__ xr = x   + (size_t)row * VPR;
    float4*       __restrict__ yr = out + (size_t)row * VPR;

    const int b0 = s >> 2;                       // first (possibly partial) masked vec
    const int b1 = (b0 + 2048) & VM1;            // vec containing mask end
    const int k0 = (b1 + 1) & VM1;               // kept stream base

    // Main uniform loop: zero vec (b0+1+j), copy vecs k0+j, k0+2047+j, k0+4094+j.
    const int jend = min(JTOT, (split + 1) * JSPAN);
    const float4 z = make_float4(0.f, 0.f, 0.f, 0.f);

    #pragma unroll 2
    for (int j = split * JSPAN + threadIdx.x; j < jend; j += THREADS) {
        const int mz = (b0 + 1 + j)    & VM1;
        const int c0 = (k0 + j)        & VM1;
        const int c1 = (k0 + 2047 + j) & VM1;
        const int c2 = (k0 + 4094 + j) & VM1;
        float4 v0 = xr[c0];
        float4 v1 = xr[c1];
        float4 v2 = xr[c2];
        yr[mz] = z;
        yr[c0] = v0;
        yr[c1] = v1;
        yr[c2] = v2;
    }

    // Edge vectors (4 per row): boundary vecs b0, b1 (partial mask) and the
    // 2 kept remainder vecs. Full per-lane select path.
    if (split == 0 && threadIdx.x < 4) {
        const int t = threadIdx.x;
        const int v = (t == 0) ? b0
                    : (t == 1) ? b1
                    : (t == 2) ? ((k0 + 6141) & VM1)
                               : ((k0 + 6142) & VM1);
        float4 w = xr[v];
        const int base = v << 2;
        const int o0 = (base     - s) & LM1;
        const int o1 = (base + 1 - s) & LM1;
        const int o2 = (base + 2 - s) & LM1;
        const int o3 = (base + 3 - s) & LM1;
        w.x = (o0 < ML) ? 0.0f : w.x;
        w.y = (o1 < ML) ? 0.0f : w.y;
        w.z = (o2 < ML) ? 0.0f : w.z;
        w.w = (o3 < ML) ? 0.0f : w.w;
        yr[v] = w;
    }
}

extern "C" void kernel_launch(void* const* d_in, const int* in_sizes, int n_in,
                              void* d_out, int out_size)
{
    const float4* x      = (const float4*)d_in[0];
    const int*    starts = (const int*)d_in[1];
    float4*       out    = (float4*)d_out;

    const int n_rows = in_sizes[1];               // 128*12 = 1536
    random_time_mask_kernel<<<n_rows * SPLITS, THREADS>>>(x, starts, out);
}